// round 3
// baseline (speedup 1.0000x reference)
#include <cuda_runtime.h>
#include <math.h>

#define BB 16
#define SS 512
#define HH 1024
#define KSLOT 32
#define EE 1024
#define MROWS (BB * KSLOT)   // 512

// ---------------- scratch ----------------
__device__ float g_naf[BB * HH];
__device__ float g_ch [BB * HH];
__device__ float g_fn [MROWS * HH];
__device__ float g_Wa [HH * HH];
__device__ float g_Wb [HH * HH];
__device__ float g_A  [MROWS * HH];
__device__ float g_Bm [MROWS * HH];
__device__ float g_Hn [MROWS * HH];
__device__ float g_part[2 * 3 * MROWS * HH];   // split-K partials [s][z][512*1024]
__device__ int   g_m  [BB];

__device__ __forceinline__ float tanh_fast(float x) {
    float r;
    asm("tanh.approx.f32 %0, %1;" : "=f"(r) : "f"(x));
    return r;
}

// ---------------- 1) fused: fold edge weights + cls token heads ----------------
// blocks [0,4096): prep_w ; blocks [4096,4160): cls (16 b x 4 col-blocks)
__global__ void prep_fused(const float* __restrict__ eW,
                           const float* __restrict__ seq,
                           const float* __restrict__ nafW, const float* __restrict__ nafb,
                           const float* __restrict__ cdW,  const float* __restrict__ cdb) {
    __shared__ float s_x[HH];
    int blk = blockIdx.x;
    int tid = threadIdx.x;
    if (blk < 4096) {
        int idx = blk * 256 + tid;
        float w0 = eW[idx];
        float w1 = eW[HH * HH + idx];
        float w2 = eW[2 * HH * HH + idx];
        g_Wa[idx] = w0 + w2;
        g_Wb[idx] = w1 - w2;
    } else {
        int blkc = blk - 4096;
        int b = blkc >> 2;
        int c = (blkc & 3) * 256 + tid;
        for (int h = tid; h < HH; h += 256) s_x[h] = seq[(size_t)b * SS * HH + h];
        __syncthreads();
        float an = 0.f, ac = 0.f;
        for (int k = 0; k < HH; k++) {
            float x = s_x[k];
            an = fmaf(x, nafW[(size_t)k * HH + c], an);
            ac = fmaf(x, cdW [(size_t)k * HH + c], ac);
        }
        g_naf[b * HH + c] = an + nafb[c];
        g_ch [b * HH + c] = tanhf(ac + cdb[c]);
    }
}

// ---------------- 2) segment means -> full_nodes ----------------
__global__ void nodes_kernel(const float* __restrict__ seq, const int* __restrict__ off) {
    int b = blockIdx.x, k = blockIdx.y, tid = threadIdx.x;
    const int* po = off + b * KSLOT;
    int n = 0;
    #pragma unroll
    for (int t = 1; t < KSLOT; t++) n += (po[t] > 0);
    float* dst = g_fn + ((size_t)(b * KSLOT + k)) * HH;
    if (k < n) {
        int start = (k == 0) ? 1 : po[k] + 1;
        int end   = po[k + 1];
        float inv = 1.0f / (float)(end - start + 1);
        for (int h = tid; h < HH; h += 128) {
            float acc = 0.f;
            for (int r = start; r <= end; r++) acc += seq[((size_t)b * SS + r) * HH + h];
            dst[h] = acc * inv;
        }
    } else if (k == n) {
        for (int h = tid; h < HH; h += 128) dst[h] = g_naf[b * HH + h];
    } else {
        for (int h = tid; h < HH; h += 128) dst[h] = 0.f;
    }
    if (k == 0 && tid == 0) g_m[b] = n + 1;
}

// ---------------- 3) big GEMM, split-K=2 ----------------
// BM=64, BN=128, BK=8, 128 threads, 8x8 microtile, double-buffered.
// blockIdx.z in [0,6): z = bz>>1 (weight select), s = bz&1 (K half).
__global__ __launch_bounds__(128) void big_gemm(const float* __restrict__ ndW) {
    const int BM = 64, BN = 128, BK = 8;
    __shared__ __align__(16) float Xs[2][BK][BM + 4];
    __shared__ __align__(16) float Ws[2][BK][BN];

    int bz = blockIdx.z;
    int z = bz >> 1;
    int s = bz & 1;
    const float* Wp = (z == 0) ? ndW : (z == 1) ? g_Wa : g_Wb;
    float* Pp = g_part + (size_t)(s * 3 + z) * MROWS * HH;

    int bm = blockIdx.x * BM, bn = blockIdx.y * BN;
    int tid = threadIdx.x;
    int tx = tid & 15;     // 16 col groups of 8
    int ty = tid >> 4;     // 8 row groups of 8

    const int H4 = HH / 4;
    const float4* Xg = (const float4*)g_fn;
    const float4* Wg = (const float4*)Wp;

    // X loader: 128 float4 chunks: kq = tid>>6, xrow = tid&63
    int xkq  = tid >> 6;
    int xrow = tid & 63;
    // W loader: 256 chunks, thread gets tid and tid+128: wk = tid>>5 and 4+(tid>>5), wnq = tid&31
    int wk  = tid >> 5;
    int wnq = tid & 31;

    const int kbase = s * (HH / 2);
    const int NT = (HH / 2) / BK;   // 64 k-tiles per half

    float4 xa, wa, wb;
    {
        int k0 = kbase;
        xa = Xg[(size_t)(bm + xrow) * H4 + (k0 >> 2) + xkq];
        wa = Wg[(size_t)(k0 + wk) * H4 + (bn >> 2) + wnq];
        wb = Wg[(size_t)(k0 + 4 + wk) * H4 + (bn >> 2) + wnq];
    }
    Xs[0][xkq * 4 + 0][xrow] = xa.x; Xs[0][xkq * 4 + 1][xrow] = xa.y;
    Xs[0][xkq * 4 + 2][xrow] = xa.z; Xs[0][xkq * 4 + 3][xrow] = xa.w;
    *(float4*)&Ws[0][wk][wnq * 4]     = wa;
    *(float4*)&Ws[0][4 + wk][wnq * 4] = wb;
    __syncthreads();

    float acc[8][8];
    #pragma unroll
    for (int i = 0; i < 8; i++)
        #pragma unroll
        for (int j = 0; j < 8; j++) acc[i][j] = 0.f;

    int buf = 0;
    for (int kt = 0; kt < NT; kt++) {
        if (kt + 1 < NT) {
            int k0 = kbase + (kt + 1) * BK;
            xa = Xg[(size_t)(bm + xrow) * H4 + (k0 >> 2) + xkq];
            wa = Wg[(size_t)(k0 + wk) * H4 + (bn >> 2) + wnq];
            wb = Wg[(size_t)(k0 + 4 + wk) * H4 + (bn >> 2) + wnq];
        }
        #pragma unroll
        for (int kk = 0; kk < BK; kk++) {
            float4 x0 = *(const float4*)&Xs[buf][kk][ty * 8];
            float4 x1 = *(const float4*)&Xs[buf][kk][ty * 8 + 4];
            float4 w0 = *(const float4*)&Ws[buf][kk][tx * 8];
            float4 w1 = *(const float4*)&Ws[buf][kk][tx * 8 + 4];
            float xr[8] = {x0.x, x0.y, x0.z, x0.w, x1.x, x1.y, x1.z, x1.w};
            float wr[8] = {w0.x, w0.y, w0.z, w0.w, w1.x, w1.y, w1.z, w1.w};
            #pragma unroll
            for (int i = 0; i < 8; i++)
                #pragma unroll
                for (int j = 0; j < 8; j++)
                    acc[i][j] = fmaf(xr[i], wr[j], acc[i][j]);
        }
        if (kt + 1 < NT) {
            int nb = buf ^ 1;
            Xs[nb][xkq * 4 + 0][xrow] = xa.x; Xs[nb][xkq * 4 + 1][xrow] = xa.y;
            Xs[nb][xkq * 4 + 2][xrow] = xa.z; Xs[nb][xkq * 4 + 3][xrow] = xa.w;
            *(float4*)&Ws[nb][wk][wnq * 4]     = wa;
            *(float4*)&Ws[nb][4 + wk][wnq * 4] = wb;
            __syncthreads();
            buf = nb;
        }
    }

    #pragma unroll
    for (int i = 0; i < 8; i++) {
        int r = bm + ty * 8 + i;
        float* cr = Pp + (size_t)r * HH + bn + tx * 8;
        *(float4*)(cr)     = make_float4(acc[i][0], acc[i][1], acc[i][2], acc[i][3]);
        *(float4*)(cr + 4) = make_float4(acc[i][4], acc[i][5], acc[i][6], acc[i][7]);
    }
}

// ---------------- 4) split-K reduce (+ bias/tanh for z==0) ----------------
__global__ void reduce_kernel(const float* __restrict__ ndb) {
    int z = blockIdx.y;
    int t4 = blockIdx.x * 256 + threadIdx.x;   // [0, 131072) float4s
    const float4* gp4 = (const float4*)g_part;
    float4 a = gp4[(size_t)(0 * 3 + z) * (MROWS * HH / 4) + t4];
    float4 b = gp4[(size_t)(1 * 3 + z) * (MROWS * HH / 4) + t4];
    float4 r = make_float4(a.x + b.x, a.y + b.y, a.z + b.z, a.w + b.w);
    float4* dst = (float4*)((z == 0) ? g_Hn : (z == 1) ? g_A : g_Bm);
    if (z == 0) {
        int c = (t4 & 255) * 4;
        r.x = tanhf(r.x + ndb[c]);
        r.y = tanhf(r.y + ndb[c + 1]);
        r.z = tanhf(r.z + ndb[c + 2]);
        r.w = tanhf(r.w + ndb[c + 3]);
    }
    dst[t4] = r;
}

// ---------------- 5) tail: node+cls logits, then edges ----------------
// blocks [0,528): logits rows. blocks [528, 528+16*33): edges (b, i).
__global__ __launch_bounds__(256) void tail_kernel(
        const float* __restrict__ noW, const float* __restrict__ nob,
        const float* __restrict__ coW, const float* __restrict__ cob,
        const float* __restrict__ eb,
        const float* __restrict__ eoW, const float* __restrict__ eob,
        float* __restrict__ out) {
    __shared__ __align__(16) float s_B[HH];
    __shared__ __align__(16) float s_eb[HH];
    __shared__ __align__(16) float s_w0[HH];
    __shared__ __align__(16) float s_w1[HH];
    __shared__ float sred[16];
    int blk = blockIdx.x;
    int tid = threadIdx.x;
    int lane = tid & 31, wid = tid >> 5;

    if (blk < 528) {
        // ---- logits row ----
        const float* src;
        const float* Wv;
        const float* bv;
        float* dst;
        if (blk < MROWS) {
            src = g_Hn + (size_t)blk * HH; Wv = noW; bv = nob; dst = out + 32 + blk * 2;
        } else {
            int b = blk - MROWS;
            src = g_ch + (size_t)b * HH;  Wv = coW; bv = cob; dst = out + b * 2;
        }
        float p0 = 0.f, p1 = 0.f;
        for (int h = tid; h < HH; h += 256) {
            float v = src[h];
            p0 = fmaf(v, Wv[h * 2],     p0);
            p1 = fmaf(v, Wv[h * 2 + 1], p1);
        }
        #pragma unroll
        for (int o = 16; o > 0; o >>= 1) {
            p0 += __shfl_down_sync(0xffffffffu, p0, o);
            p1 += __shfl_down_sync(0xffffffffu, p1, o);
        }
        if (lane == 0) { sred[wid * 2] = p0; sred[wid * 2 + 1] = p1; }
        __syncthreads();
        if (tid == 0) {
            float a0 = 0.f, a1 = 0.f;
            for (int w = 0; w < 8; w++) { a0 += sred[w * 2]; a1 += sred[w * 2 + 1]; }
            dst[0] = a0 + bv[0]; dst[1] = a1 + bv[1];
        }
        return;
    }

    // ---- edges ----
    int eidx = blk - 528;
    int b = eidx / (KSLOT + 1);
    int i = eidx - b * (KSLOT + 1);
    int m = g_m[b];
    float* outp = out + 32 + MROWS * 2;   // edge logits start

    for (int h = tid; h < HH; h += 256) {
        s_eb[h] = eb[h];
        s_w0[h] = eoW[h * 2];
        s_w1[h] = eoW[h * 2 + 1];
    }
    if (i < KSLOT && i < m) {
        for (int h = tid; h < HH; h += 256)
            s_B[h] = g_Bm[((size_t)(b * KSLOT + i)) * HH + h];
    }
    __syncthreads();

    if (i < KSLOT) {
        if (i >= m) return;
        // warp-per-j
        for (int j = wid; j < m; j += 8) {
            const float4* Aj = (const float4*)(g_A + ((size_t)(b * KSLOT + j)) * HH);
            float p0 = 0.f, p1 = 0.f;
            #pragma unroll
            for (int it = 0; it < 8; it++) {
                int h4 = it * 32 + lane;
                float4 a  = Aj[h4];
                float4 bv = *(const float4*)&s_B[h4 * 4];
                float4 ev = *(const float4*)&s_eb[h4 * 4];
                float4 w0 = *(const float4*)&s_w0[h4 * 4];
                float4 w1 = *(const float4*)&s_w1[h4 * 4];
                float v0 = tanh_fast(a.x + bv.x + ev.x);
                float v1 = tanh_fast(a.y + bv.y + ev.y);
                float v2 = tanh_fast(a.z + bv.z + ev.z);
                float v3 = tanh_fast(a.w + bv.w + ev.w);
                p0 = fmaf(v0, w0.x, fmaf(v1, w0.y, fmaf(v2, w0.z, fmaf(v3, w0.w, p0))));
                p1 = fmaf(v0, w1.x, fmaf(v1, w1.y, fmaf(v2, w1.z, fmaf(v3, w1.w, p1))));
            }
            #pragma unroll
            for (int o = 16; o > 0; o >>= 1) {
                p0 += __shfl_down_sync(0xffffffffu, p0, o);
                p1 += __shfl_down_sync(0xffffffffu, p1, o);
            }
            if (lane == 0) {
                int e = i * m + j;
                outp[((size_t)b * EE + e) * 2]     = p0 + eob[0];
                outp[((size_t)b * EE + e) * 2 + 1] = p1 + eob[1];
            }
        }
    } else {
        // invalid-edge constant: tanh(edge_bias) . eoW + eob  (precise tanh, cheap)
        float p0 = 0.f, p1 = 0.f;
        for (int h = tid; h < HH; h += 256) {
            float v = tanhf(s_eb[h]);
            p0 = fmaf(v, s_w0[h], p0);
            p1 = fmaf(v, s_w1[h], p1);
        }
        #pragma unroll
        for (int o = 16; o > 0; o >>= 1) {
            p0 += __shfl_down_sync(0xffffffffu, p0, o);
            p1 += __shfl_down_sync(0xffffffffu, p1, o);
        }
        if (lane == 0) { sred[wid * 2] = p0; sred[wid * 2 + 1] = p1; }
        __syncthreads();
        if (tid == 0) {
            float a0 = 0.f, a1 = 0.f;
            for (int w = 0; w < 8; w++) { a0 += sred[w * 2]; a1 += sred[w * 2 + 1]; }
            sred[0] = a0 + eob[0]; sred[1] = a1 + eob[1];
        }
        __syncthreads();
        float c0 = sred[0], c1 = sred[1];
        for (int e = m * m + tid; e < EE; e += 256) {
            outp[((size_t)b * EE + e) * 2]     = c0;
            outp[((size_t)b * EE + e) * 2 + 1] = c1;
        }
    }
}

// ---------------- launch ----------------
extern "C" void kernel_launch(void* const* d_in, const int* in_sizes, int n_in,
                              void* d_out, int out_size) {
    const float* seq  = (const float*)d_in[0];
    const int*   off  = (const int*)  d_in[1];
    const float* nafW = (const float*)d_in[2];
    const float* nafb = (const float*)d_in[3];
    const float* cdW  = (const float*)d_in[4];
    const float* cdb  = (const float*)d_in[5];
    const float* coW  = (const float*)d_in[6];
    const float* cob  = (const float*)d_in[7];
    const float* ndW  = (const float*)d_in[8];
    const float* ndb  = (const float*)d_in[9];
    const float* noW  = (const float*)d_in[10];
    const float* nob  = (const float*)d_in[11];
    const float* edW  = (const float*)d_in[12];
    const float* edb  = (const float*)d_in[13];
    const float* eoW  = (const float*)d_in[14];
    const float* eob  = (const float*)d_in[15];
    float* out = (float*)d_out;

    prep_fused<<<4160, 256>>>(edW, seq, nafW, nafb, cdW, cdb);
    nodes_kernel<<<dim3(BB, KSLOT), 128>>>(seq, off);
    big_gemm<<<dim3(512 / 64, HH / 128, 6), 128>>>(ndW);
    reduce_kernel<<<dim3(512, 3), 256>>>(ndb);
    tail_kernel<<<528 + BB * (KSLOT + 1), 256>>>(noW, nob, coW, cob, edb, eoW, eob, out);
}

// round 7
// speedup vs baseline: 1.3665x; 1.3665x over previous
#include <cuda_runtime.h>
#include <math.h>

#define BB 16
#define SS 512
#define HH 1024
#define KSLOT 32
#define EE 1024
#define MROWS (BB * KSLOT)   // 512

// ---------------- scratch ----------------
__device__ float g_naf[BB * HH];
__device__ float g_ch [BB * HH];
__device__ float g_fn [MROWS * HH];
__device__ float g_Xhi[MROWS * HH];
__device__ float g_Xlo[MROWS * HH];
__device__ float g_Whi[3 * HH * HH];   // z: 0=node_dense, 1=Wa(=W0+W2), 2=Wb(=W1-W2)
__device__ float g_Wlo[3 * HH * HH];
__device__ float g_A  [MROWS * HH];
__device__ float g_Bm [MROWS * HH];
__device__ float g_Hn [MROWS * HH];
__device__ int   g_m  [BB];

__device__ __forceinline__ float tanh_fast(float x) {
    float r;
    asm("tanh.approx.f32 %0, %1;" : "=f"(r) : "f"(x));
    return r;
}
__device__ __forceinline__ float tf32_hi(float x) {
    unsigned u;
    asm("cvt.rna.tf32.f32 %0, %1;" : "=r"(u) : "f"(x));
    return __uint_as_float(u);
}
__device__ __forceinline__ void split2(float x, float& hi, float& lo) {
    hi = tf32_hi(x);
    lo = tf32_hi(x - hi);
}

// ---------------- 1) fused: fold+split weights, cls token heads ----------------
// blocks [0,4096): weight prep ; blocks [4096,4160): cls (16 b x 4 col-blocks)
__global__ void prep_fused(const float* __restrict__ eW, const float* __restrict__ ndW,
                           const float* __restrict__ seq,
                           const float* __restrict__ nafW, const float* __restrict__ nafb,
                           const float* __restrict__ cdW,  const float* __restrict__ cdb) {
    __shared__ float s_x[HH];
    int blk = blockIdx.x;
    int tid = threadIdx.x;
    if (blk < 4096) {
        int idx = blk * 256 + tid;
        float w0 = eW[idx];
        float w1 = eW[HH * HH + idx];
        float w2 = eW[2 * HH * HH + idx];
        float nd = ndW[idx];
        float h, l;
        split2(nd,      h, l); g_Whi[idx] = h;                g_Wlo[idx] = l;
        split2(w0 + w2, h, l); g_Whi[HH * HH + idx] = h;      g_Wlo[HH * HH + idx] = l;
        split2(w1 - w2, h, l); g_Whi[2 * HH * HH + idx] = h;  g_Wlo[2 * HH * HH + idx] = l;
    } else {
        int blkc = blk - 4096;
        int b = blkc >> 2;
        int c = (blkc & 3) * 256 + tid;
        for (int h = tid; h < HH; h += 256) s_x[h] = seq[(size_t)b * SS * HH + h];
        __syncthreads();
        float an = 0.f, ac = 0.f;
        for (int k = 0; k < HH; k++) {
            float x = s_x[k];
            an = fmaf(x, nafW[(size_t)k * HH + c], an);
            ac = fmaf(x, cdW [(size_t)k * HH + c], ac);
        }
        g_naf[b * HH + c] = an + nafb[c];
        g_ch [b * HH + c] = tanhf(ac + cdb[c]);
    }
}

// ---------------- 2) segment means -> full_nodes ----------------
__global__ void nodes_kernel(const float* __restrict__ seq, const int* __restrict__ off) {
    int b = blockIdx.x, k = blockIdx.y, tid = threadIdx.x;
    const int* po = off + b * KSLOT;
    int n = 0;
    #pragma unroll
    for (int t = 1; t < KSLOT; t++) n += (po[t] > 0);
    float* dst = g_fn + ((size_t)(b * KSLOT + k)) * HH;
    if (k < n) {
        int start = (k == 0) ? 1 : po[k] + 1;
        int end   = po[k + 1];
        float inv = 1.0f / (float)(end - start + 1);
        for (int h = tid; h < HH; h += 128) {
            float acc = 0.f;
            for (int r = start; r <= end; r++) acc += seq[((size_t)b * SS + r) * HH + h];
            dst[h] = acc * inv;
        }
    } else if (k == n) {
        for (int h = tid; h < HH; h += 128) dst[h] = g_naf[b * HH + h];
    } else {
        for (int h = tid; h < HH; h += 128) dst[h] = 0.f;
    }
    if (k == 0 && tid == 0) g_m[b] = n + 1;
}

// ---------------- 2b) split X into tf32 hi/lo ----------------
__global__ void split_x() {
    int i = blockIdx.x * 256 + threadIdx.x;      // 131072 float4s
    float4 v = ((const float4*)g_fn)[i];
    float4 h4, l4;
    split2(v.x, h4.x, l4.x);
    split2(v.y, h4.y, l4.y);
    split2(v.z, h4.z, l4.z);
    split2(v.w, h4.w, l4.w);
    ((float4*)g_Xhi)[i] = h4;
    ((float4*)g_Xlo)[i] = l4;
}

// ---------------- 3) tensor-core GEMM (3xTF32) ----------------
// C[512,1024] = X @ W[z], z in {0,1,2}. BM=64, BN=64, BK=32, 128 thr (2x2 warps).
__device__ __forceinline__ void mma8(float* c, const unsigned* a, const unsigned* b) {
    asm volatile(
        "mma.sync.aligned.m16n8k8.row.col.f32.tf32.tf32.f32 "
        "{%0,%1,%2,%3}, {%4,%5,%6,%7}, {%8,%9}, {%0,%1,%2,%3};"
        : "+f"(c[0]), "+f"(c[1]), "+f"(c[2]), "+f"(c[3])
        : "r"(a[0]), "r"(a[1]), "r"(a[2]), "r"(a[3]), "r"(b[0]), "r"(b[1]));
}

__global__ __launch_bounds__(128) void mma_gemm(const float* __restrict__ ndb) {
    const int BK = 32, PAD = 76;
    __shared__ float sAh[BK][PAD];
    __shared__ float sAl[BK][PAD];
    __shared__ float sBh[BK][PAD];
    __shared__ float sBl[BK][PAD];

    int z = blockIdx.z;
    float* Cp = (z == 0) ? g_Hn : (z == 1) ? g_A : g_Bm;
    const float* Whz = g_Whi + (size_t)z * HH * HH;
    const float* Wlz = g_Wlo + (size_t)z * HH * HH;

    int bm = blockIdx.x * 64, bn = blockIdx.y * 64;
    int tid = threadIdx.x;
    int warp = tid >> 5, lane = tid & 31;
    int warpM = warp >> 1, warpN = warp & 1;
    int g = lane >> 2, tg = lane & 3;

    // loader indices
    int acol4 = tid & 7;        // k-group (4 k's each)
    int arb   = tid >> 3;       // 0..15, rows arb + 16*rr
    int bkr   = tid >> 4;       // 0..7, k rows bkr + 8*kk
    int bn4   = tid & 15;       // n float4 group

    float acc[2][4][4];
    #pragma unroll
    for (int mt = 0; mt < 2; mt++)
        #pragma unroll
        for (int nt = 0; nt < 4; nt++)
            #pragma unroll
            for (int r = 0; r < 4; r++) acc[mt][nt][r] = 0.f;

    for (int kt = 0; kt < HH / BK; kt++) {
        int k0 = kt * BK;
        // load A tile (64 x 32) hi+lo, scatter to k-major smem
        #pragma unroll
        for (int rr = 0; rr < 4; rr++) {
            int r = arb + rr * 16;
            float4 vh = *(const float4*)&g_Xhi[(size_t)(bm + r) * HH + k0 + acol4 * 4];
            float4 vl = *(const float4*)&g_Xlo[(size_t)(bm + r) * HH + k0 + acol4 * 4];
            sAh[acol4 * 4 + 0][r] = vh.x; sAh[acol4 * 4 + 1][r] = vh.y;
            sAh[acol4 * 4 + 2][r] = vh.z; sAh[acol4 * 4 + 3][r] = vh.w;
            sAl[acol4 * 4 + 0][r] = vl.x; sAl[acol4 * 4 + 1][r] = vl.y;
            sAl[acol4 * 4 + 2][r] = vl.z; sAl[acol4 * 4 + 3][r] = vl.w;
        }
        // load B tile (32 x 64) hi+lo
        #pragma unroll
        for (int kk = 0; kk < 4; kk++) {
            int k = bkr + kk * 8;
            float4 vh = *(const float4*)&Whz[(size_t)(k0 + k) * HH + bn + bn4 * 4];
            float4 vl = *(const float4*)&Wlz[(size_t)(k0 + k) * HH + bn + bn4 * 4];
            *(float4*)&sBh[k][bn4 * 4] = vh;
            *(float4*)&sBl[k][bn4 * 4] = vl;
        }
        __syncthreads();

        #pragma unroll
        for (int ks = 0; ks < 4; ks++) {
            int kk = ks * 8;
            unsigned ah[2][4], al[2][4], bh[4][2], bl[4][2];
            #pragma unroll
            for (int mt = 0; mt < 2; mt++) {
                int mb = warpM * 32 + mt * 16;
                ah[mt][0] = __float_as_uint(sAh[kk + tg][mb + g]);
                ah[mt][1] = __float_as_uint(sAh[kk + tg][mb + g + 8]);
                ah[mt][2] = __float_as_uint(sAh[kk + tg + 4][mb + g]);
                ah[mt][3] = __float_as_uint(sAh[kk + tg + 4][mb + g + 8]);
                al[mt][0] = __float_as_uint(sAl[kk + tg][mb + g]);
                al[mt][1] = __float_as_uint(sAl[kk + tg][mb + g + 8]);
                al[mt][2] = __float_as_uint(sAl[kk + tg + 4][mb + g]);
                al[mt][3] = __float_as_uint(sAl[kk + tg + 4][mb + g + 8]);
            }
            #pragma unroll
            for (int nt = 0; nt < 4; nt++) {
                int nb = warpN * 32 + nt * 8;
                bh[nt][0] = __float_as_uint(sBh[kk + tg][nb + g]);
                bh[nt][1] = __float_as_uint(sBh[kk + tg + 4][nb + g]);
                bl[nt][0] = __float_as_uint(sBl[kk + tg][nb + g]);
                bl[nt][1] = __float_as_uint(sBl[kk + tg + 4][nb + g]);
            }
            #pragma unroll
            for (int mt = 0; mt < 2; mt++)
                #pragma unroll
                for (int nt = 0; nt < 4; nt++) {
                    mma8(acc[mt][nt], ah[mt], bh[nt]);
                    mma8(acc[mt][nt], al[mt], bh[nt]);
                    mma8(acc[mt][nt], ah[mt], bl[nt]);
                }
        }
        __syncthreads();
    }

    // epilogue
    #pragma unroll
    for (int mt = 0; mt < 2; mt++) {
        #pragma unroll
        for (int half = 0; half < 2; half++) {
            int m = bm + warpM * 32 + mt * 16 + g + half * 8;
            #pragma unroll
            for (int nt = 0; nt < 4; nt++) {
                int n = bn + warpN * 32 + nt * 8 + tg * 2;
                float v0 = acc[mt][nt][half * 2];
                float v1 = acc[mt][nt][half * 2 + 1];
                if (z == 0) {
                    v0 = tanhf(v0 + ndb[n]);
                    v1 = tanhf(v1 + ndb[n + 1]);
                }
                *(float2*)&Cp[(size_t)m * HH + n] = make_float2(v0, v1);
            }
        }
    }
}

// ---------------- 4) tail: node+cls logits, then edges ----------------
__global__ __launch_bounds__(256) void tail_kernel(
        const float* __restrict__ noW, const float* __restrict__ nob,
        const float* __restrict__ coW, const float* __restrict__ cob,
        const float* __restrict__ eb,
        const float* __restrict__ eoW, const float* __restrict__ eob,
        float* __restrict__ out) {
    __shared__ __align__(16) float s_B[HH];
    __shared__ __align__(16) float s_eb[HH];
    __shared__ __align__(16) float s_w0[HH];
    __shared__ __align__(16) float s_w1[HH];
    __shared__ float sred[16];
    int blk = blockIdx.x;
    int tid = threadIdx.x;
    int lane = tid & 31, wid = tid >> 5;

    if (blk < 528) {
        const float* src;
        const float* Wv;
        const float* bv;
        float* dst;
        if (blk < MROWS) {
            src = g_Hn + (size_t)blk * HH; Wv = noW; bv = nob; dst = out + 32 + blk * 2;
        } else {
            int b = blk - MROWS;
            src = g_ch + (size_t)b * HH;  Wv = coW; bv = cob; dst = out + b * 2;
        }
        float p0 = 0.f, p1 = 0.f;
        for (int h = tid; h < HH; h += 256) {
            float v = src[h];
            p0 = fmaf(v, Wv[h * 2],     p0);
            p1 = fmaf(v, Wv[h * 2 + 1], p1);
        }
        #pragma unroll
        for (int o = 16; o > 0; o >>= 1) {
            p0 += __shfl_down_sync(0xffffffffu, p0, o);
            p1 += __shfl_down_sync(0xffffffffu, p1, o);
        }
        if (lane == 0) { sred[wid * 2] = p0; sred[wid * 2 + 1] = p1; }
        __syncthreads();
        if (tid == 0) {
            float a0 = 0.f, a1 = 0.f;
            for (int w = 0; w < 8; w++) { a0 += sred[w * 2]; a1 += sred[w * 2 + 1]; }
            dst[0] = a0 + bv[0]; dst[1] = a1 + bv[1];
        }
        return;
    }

    int eidx = blk - 528;
    int b = eidx / (KSLOT + 1);
    int i = eidx - b * (KSLOT + 1);
    int m = g_m[b];
    float* outp = out + 32 + MROWS * 2;

    for (int h = tid; h < HH; h += 256) {
        s_eb[h] = eb[h];
        s_w0[h] = eoW[h * 2];
        s_w1[h] = eoW[h * 2 + 1];
    }
    if (i < KSLOT && i < m) {
        for (int h = tid; h < HH; h += 256)
            s_B[h] = g_Bm[((size_t)(b * KSLOT + i)) * HH + h];
    }
    __syncthreads();

    if (i < KSLOT) {
        if (i >= m) return;
        for (int j = wid; j < m; j += 8) {
            const float4* Aj = (const float4*)(g_A + ((size_t)(b * KSLOT + j)) * HH);
            float p0 = 0.f, p1 = 0.f;
            #pragma unroll
            for (int it = 0; it < 8; it++) {
                int h4 = it * 32 + lane;
                float4 a  = Aj[h4];
                float4 bv = *(const float4*)&s_B[h4 * 4];
                float4 ev = *(const float4*)&s_eb[h4 * 4];
                float4 w0 = *(const float4*)&s_w0[h4 * 4];
                float4 w1 = *(const float4*)&s_w1[h4 * 4];
                float v0 = tanh_fast(a.x + bv.x + ev.x);
                float v1 = tanh_fast(a.y + bv.y + ev.y);
                float v2 = tanh_fast(a.z + bv.z + ev.z);
                float v3 = tanh_fast(a.w + bv.w + ev.w);
                p0 = fmaf(v0, w0.x, fmaf(v1, w0.y, fmaf(v2, w0.z, fmaf(v3, w0.w, p0))));
                p1 = fmaf(v0, w1.x, fmaf(v1, w1.y, fmaf(v2, w1.z, fmaf(v3, w1.w, p1))));
            }
            #pragma unroll
            for (int o = 16; o > 0; o >>= 1) {
                p0 += __shfl_down_sync(0xffffffffu, p0, o);
                p1 += __shfl_down_sync(0xffffffffu, p1, o);
            }
            if (lane == 0) {
                int e = i * m + j;
                outp[((size_t)b * EE + e) * 2]     = p0 + eob[0];
                outp[((size_t)b * EE + e) * 2 + 1] = p1 + eob[1];
            }
        }
    } else {
        float p0 = 0.f, p1 = 0.f;
        for (int h = tid; h < HH; h += 256) {
            float v = tanhf(s_eb[h]);
            p0 = fmaf(v, s_w0[h], p0);
            p1 = fmaf(v, s_w1[h], p1);
        }
        #pragma unroll
        for (int o = 16; o > 0; o >>= 1) {
            p0 += __shfl_down_sync(0xffffffffu, p0, o);
            p1 += __shfl_down_sync(0xffffffffu, p1, o);
        }
        if (lane == 0) { sred[wid * 2] = p0; sred[wid * 2 + 1] = p1; }
        __syncthreads();
        if (tid == 0) {
            float a0 = 0.f, a1 = 0.f;
            for (int w = 0; w < 8; w++) { a0 += sred[w * 2]; a1 += sred[w * 2 + 1]; }
            sred[0] = a0 + eob[0]; sred[1] = a1 + eob[1];
        }
        __syncthreads();
        float c0 = sred[0], c1 = sred[1];
        for (int e = m * m + tid; e < EE; e += 256) {
            outp[((size_t)b * EE + e) * 2]     = c0;
            outp[((size_t)b * EE + e) * 2 + 1] = c1;
        }
    }
}

// ---------------- launch ----------------
extern "C" void kernel_launch(void* const* d_in, const int* in_sizes, int n_in,
                              void* d_out, int out_size) {
    const float* seq  = (const float*)d_in[0];
    const int*   off  = (const int*)  d_in[1];
    const float* nafW = (const float*)d_in[2];
    const float* nafb = (const float*)d_in[3];
    const float* cdW  = (const float*)d_in[4];
    const float* cdb  = (const float*)d_in[5];
    const float* coW  = (const float*)d_in[6];
    const float* cob  = (const float*)d_in[7];
    const float* ndW  = (const float*)d_in[8];
    const float* ndb  = (const float*)d_in[9];
    const float* noW  = (const float*)d_in[10];
    const float* nob  = (const float*)d_in[11];
    const float* edW  = (const float*)d_in[12];
    const float* edb  = (const float*)d_in[13];
    const float* eoW  = (const float*)d_in[14];
    const float* eob  = (const float*)d_in[15];
    float* out = (float*)d_out;

    prep_fused<<<4160, 256>>>(edW, ndW, seq, nafW, nafb, cdW, cdb);
    nodes_kernel<<<dim3(BB, KSLOT), 128>>>(seq, off);
    split_x<<<512, 256>>>();
    mma_gemm<<<dim3(512 / 64, HH / 64, 3), 128>>>(ndb);
    tail_kernel<<<528 + BB * (KSLOT + 1), 256>>>(noW, nob, coW, cob, edb, eoW, eob, out);
}